// round 12
// baseline (speedup 1.0000x reference)
#include <cuda_runtime.h>
#include <cuda_bf16.h>
#include <math.h>

#define B_CONSTF 0.9f
#define EPSF 1e-10f
#define SCALEF 0.0625f

typedef unsigned long long ull;

// ---------------- device scratch ----------------
__device__ float g_qh[16*512*32];    // per-head Q   [bh][s][32]
__device__ float g_kh[16*512*32];    // per-head K   [bh][s][32]
__device__ float g_v [1024*256];     // V row-major  [b*s][256]
__device__ float g_vz[16*512*32];    // v_norm^p     [bh][s][32]
__device__ float g_s [16*512*512];   // exp scores   [bh][q][k]  (16.8MB)
__device__ float g_lp[16*16*512];    // row-sum partials [bh][kslice16][q]
__device__ float g_e [1024*256];     // power-mean result (row-major)
__device__ float g_vmin[512], g_nscale[512], g_unscale[512];
__device__ float g_p[256], g_invp[256];

// ---------------- f32x2 helpers (SIMT kernels) ----------------
__device__ __forceinline__ ull f2pack(float lo, float hi) {
    ull r; asm("mov.b64 %0, {%1, %2};" : "=l"(r) : "f"(lo), "f"(hi)); return r;
}
__device__ __forceinline__ void f2unpack(ull v, float& lo, float& hi) {
    asm("mov.b64 {%0, %1}, %2;" : "=f"(lo), "=f"(hi) : "l"(v));
}
__device__ __forceinline__ ull f2fma(ull a, ull b, ull c) {
    ull d; asm("fma.rn.f32x2 %0, %1, %2, %3;" : "=l"(d) : "l"(a), "l"(b), "l"(c)); return d;
}

// ---------------- warp mma helper ----------------
__device__ __forceinline__ void mma_bf16(float* d, const unsigned* a, const unsigned* b) {
    asm volatile(
        "mma.sync.aligned.m16n8k16.row.col.f32.bf16.bf16.f32 "
        "{%0,%1,%2,%3}, {%4,%5,%6,%7}, {%8,%9}, {%0,%1,%2,%3};"
        : "+f"(d[0]), "+f"(d[1]), "+f"(d[2]), "+f"(d[3])
        : "r"(a[0]), "r"(a[1]), "r"(a[2]), "r"(a[3]), "r"(b[0]), "r"(b[1]));
}
// fp32 -> (hi,lo) bf16x2 words
__device__ __forceinline__ void split2(float x0, float x1, unsigned& hw, unsigned& lw) {
    __nv_bfloat16 h0 = __float2bfloat16(x0);
    __nv_bfloat16 h1 = __float2bfloat16(x1);
    __nv_bfloat16 l0 = __float2bfloat16(x0 - __bfloat162float(h0));
    __nv_bfloat16 l1 = __float2bfloat16(x1 - __bfloat162float(h1));
    hw = (unsigned)__bfloat16_as_ushort(h0) | ((unsigned)__bfloat16_as_ushort(h1) << 16);
    lw = (unsigned)__bfloat16_as_ushort(l0) | ((unsigned)__bfloat16_as_ushort(l1) << 16);
}

// =========================================================================
// Kernel 1: fused QKV projection (round-8 proven).
// =========================================================================
__global__ __launch_bounds__(256) void qkv_gemm(
    const float* __restrict__ ctx, const float* __restrict__ W_Q,
    const float* __restrict__ W_KV)
{
    __shared__ float As[16][68];
    __shared__ float Bs[16][68];
    const int tid = threadIdx.x;
    const int tx = tid & 15, ty = tid >> 4;
    const int bm = blockIdx.y * 64;
    const int bn = blockIdx.x * 64;
    const float* Bsrc = (bn < 256) ? (W_Q + (size_t)bn * 256)
                                   : (W_KV + (size_t)(bn - 256) * 256);
    const int lm = tid >> 2, lc = tid & 3;

    ull acc[4][2];
    #pragma unroll
    for (int n = 0; n < 4; n++) { acc[n][0] = 0ULL; acc[n][1] = 0ULL; }

    float4 pa = *(const float4*)&ctx [(size_t)(bm + lm) * 256 + lc*4];
    float4 pb = *(const float4*)&Bsrc[(size_t)lm * 256 + lc*4];

    for (int k0 = 0; k0 < 256; k0 += 16) {
        As[lc*4+0][lm] = pa.x; As[lc*4+1][lm] = pa.y;
        As[lc*4+2][lm] = pa.z; As[lc*4+3][lm] = pa.w;
        Bs[lc*4+0][lm] = pb.x; Bs[lc*4+1][lm] = pb.y;
        Bs[lc*4+2][lm] = pb.z; Bs[lc*4+3][lm] = pb.w;
        __syncthreads();
        if (k0 + 16 < 256) {
            pa = *(const float4*)&ctx [(size_t)(bm + lm) * 256 + k0 + 16 + lc*4];
            pb = *(const float4*)&Bsrc[(size_t)lm * 256 + k0 + 16 + lc*4];
        }
        #pragma unroll
        for (int kk = 0; kk < 16; kk++) {
            ull a0 = *(const ull*)&As[kk][ty*4];
            ull a1 = *(const ull*)&As[kk][ty*4+2];
            float4 bf = *(const float4*)&Bs[kk][tx*4];
            ull b0 = f2pack(bf.x, bf.x), b1 = f2pack(bf.y, bf.y);
            ull b2 = f2pack(bf.z, bf.z), b3 = f2pack(bf.w, bf.w);
            acc[0][0] = f2fma(b0, a0, acc[0][0]); acc[0][1] = f2fma(b0, a1, acc[0][1]);
            acc[1][0] = f2fma(b1, a0, acc[1][0]); acc[1][1] = f2fma(b1, a1, acc[1][1]);
            acc[2][0] = f2fma(b2, a0, acc[2][0]); acc[2][1] = f2fma(b2, a1, acc[2][1]);
            acc[3][0] = f2fma(b3, a0, acc[3][0]); acc[3][1] = f2fma(b3, a1, acc[3][1]);
        }
        __syncthreads();
    }

    float v[4][4];
    #pragma unroll
    for (int n = 0; n < 4; n++) {
        f2unpack(acc[n][0], v[n][0], v[n][1]);
        f2unpack(acc[n][1], v[n][2], v[n][3]);
    }
    const int c = bn + tx*4;
    #pragma unroll
    for (int r = 0; r < 4; r++) {
        int row = bm + ty*4 + r;
        float4 o = make_float4(v[0][r], v[1][r], v[2][r], v[3][r]);
        int b = row >> 9, s = row & 511;
        if (c < 256) {
            int h = c >> 5, a = c & 31;
            *(float4*)&g_qh[((size_t)((b*8+h)*512 + s))*32 + a] = o;
        } else if (c < 512) {
            int kc = c - 256, h = kc >> 5, a = kc & 31;
            *(float4*)&g_kh[((size_t)((b*8+h)*512 + s))*32 + a] = o;
        } else {
            *(float4*)&g_v[(size_t)row * 256 + (c - 512)] = o;
        }
    }
}

// =========================================================================
// Kernel 2: v min/max per (b,d) + p/invp.
// =========================================================================
__global__ __launch_bounds__(256) void vstats_kernel(const float* __restrict__ p_param) {
    __shared__ float smn[8][32], smx[8][32];
    const int b = blockIdx.y, dc = blockIdx.x;
    const int dd = threadIdx.x & 31, sl = threadIdx.x >> 5;
    const int d = dc*32 + dd;
    float mn = 1e30f, mx = -1e30f;
    const float* base = g_v + (size_t)(b*512 + sl*64) * 256 + d;
    #pragma unroll 4
    for (int i = 0; i < 64; i++) {
        float v = base[(size_t)i * 256];
        mn = fminf(mn, v); mx = fmaxf(mx, v);
    }
    smn[sl][dd] = mn; smx[sl][dd] = mx;
    __syncthreads();
    if (sl == 0) {
        #pragma unroll
        for (int t = 1; t < 8; t++) {
            mn = fminf(mn, smn[t][dd]); mx = fmaxf(mx, smx[t][dd]);
        }
        float range = mx - mn + EPSF;
        g_vmin   [b*256 + d] = mn;
        g_nscale [b*256 + d] = (1.0f - B_CONSTF) / range;
        g_unscale[b*256 + d] = range / (1.0f - B_CONSTF);
        if (b == 0) {
            float pp = p_param[d];
            float p  = 50000.0f * tanhf(0.005f * pp) + 1.0f;
            if (p == 0.0f) p = 1e-4f;
            g_p[d] = p; g_invp[d] = 1.0f / p;
        }
    }
}

// =========================================================================
// Kernel 3: vz = v_norm^p per-head.
// =========================================================================
__global__ __launch_bounds__(256) void vz_kernel() {
    __shared__ float s_p[32], s_ns[32], s_vm[32];
    const int bh = blockIdx.y, sc = blockIdx.x;
    const int b = bh >> 3, h = bh & 7;
    const int tid = threadIdx.x;
    if (tid < 32) {
        int d = h*32 + tid;
        s_p[tid]  = g_p[d];
        s_ns[tid] = g_nscale[b*256 + d];
        s_vm[tid] = g_vmin[b*256 + d];
    }
    __syncthreads();
    const int a = tid & 31, sq = tid >> 5;
    #pragma unroll
    for (int it = 0; it < 8; it++) {
        int s = sc*64 + it*8 + sq;
        float v  = g_v[(size_t)(b*512 + s) * 256 + h*32 + a];
        float vn = (v - s_vm[a]) * s_ns[a] + B_CONSTF;
        g_vz[((size_t)(bh*512 + s))*32 + a] = __expf(s_p[a] * __logf(vn));
    }
}

// =========================================================================
// Kernel 4: pass1 on warp-level bf16 MMA (mma.sync.m16n8k16, split-bf16).
// grid (8 kt, 4 qt, 16 bh) = 512 blocks, 256 thr (8 warps).
// Tile 128q x 64k, K=32. Warp w: q-chunk (w&3)*32, k-chunk (w>>2)*32.
// S = Qh*Kh^T + Ql*Kh^T + Qh*Kl^T  (fp32 accum, ~fp32 accuracy).
// Row-sum partials: g_lp[bh][kt*2 + wk][q]  (16 partials per (bh,q)).
// =========================================================================
#define PSW 18   // padded row stride in 32-bit words (36 bf16 = 72B)

__global__ __launch_bounds__(256, 1) void pass1_mma() {
    __shared__ unsigned Qhi[128*PSW], Qlo[128*PSW];
    __shared__ unsigned Khi[64*PSW],  Klo[64*PSW];
    const int tid = threadIdx.x, lane = tid & 31, w = tid >> 5;
    const int kt = blockIdx.x, qt = blockIdx.y, bh = blockIdx.z;
    const int tig = lane & 3, grp = lane >> 2;

    // ---- fill Q: 128 rows x 32 cols, thread -> (row = tid>>1, half = tid&1)
    {
        int row = tid >> 1, half = tid & 1;
        const float* src = g_qh + ((size_t)bh*512 + qt*128 + row)*32 + half*16;
        #pragma unroll
        for (int j = 0; j < 8; j++) {
            unsigned hw, lw;
            split2(src[2*j], src[2*j+1], hw, lw);
            Qhi[row*PSW + half*8 + j] = hw;
            Qlo[row*PSW + half*8 + j] = lw;
        }
    }
    // ---- fill K: 64 rows x 32 cols (threads 0..127)
    if (tid < 128) {
        int row = tid >> 1, half = tid & 1;
        const float* src = g_kh + ((size_t)bh*512 + kt*64 + row)*32 + half*16;
        #pragma unroll
        for (int j = 0; j < 8; j++) {
            unsigned hw, lw;
            split2(src[2*j], src[2*j+1], hw, lw);
            Khi[row*PSW + half*8 + j] = hw;
            Klo[row*PSW + half*8 + j] = lw;
        }
    }
    __syncthreads();

    const int wq = (w & 3) * 32;   // q offset in tile
    const int wk = (w >> 2) * 32;  // k offset in tile

    float d[2][4][4];
    #pragma unroll
    for (int mt = 0; mt < 2; mt++)
        #pragma unroll
        for (int nt = 0; nt < 4; nt++)
            #pragma unroll
            for (int i = 0; i < 4; i++) d[mt][nt][i] = 0.f;

    #pragma unroll
    for (int mt = 0; mt < 2; mt++) {
        // A fragments for both k16 chunks, hi and lo
        unsigned ah[2][4], al[2][4];
        #pragma unroll
        for (int kc = 0; kc < 2; kc++) {
            int r0 = (wq + mt*16 + grp) * PSW + kc*8 + tig;
            int r1 = r0 + 8*PSW;
            ah[kc][0] = Qhi[r0];     ah[kc][1] = Qhi[r1];
            ah[kc][2] = Qhi[r0 + 4]; ah[kc][3] = Qhi[r1 + 4];
            al[kc][0] = Qlo[r0];     al[kc][1] = Qlo[r1];
            al[kc][2] = Qlo[r0 + 4]; al[kc][3] = Qlo[r1 + 4];
        }
        #pragma unroll
        for (int nt = 0; nt < 4; nt++) {
            #pragma unroll
            for (int kc = 0; kc < 2; kc++) {
                int nb = (wk + nt*8 + grp) * PSW + kc*8 + tig;
                unsigned bh2[2], bl2[2];
                bh2[0] = Khi[nb]; bh2[1] = Khi[nb + 4];
                bl2[0] = Klo[nb]; bl2[1] = Klo[nb + 4];
                mma_bf16(d[mt][nt], ah[kc], bh2);   // hi*hi
                mma_bf16(d[mt][nt], al[kc], bh2);   // lo*hi
                mma_bf16(d[mt][nt], ah[kc], bl2);   // hi*lo
            }
        }
    }

    // ---- epilogue: exp, store to g_s, row-sum partials
    float* Sbase = g_s + (size_t)bh*512*512;
    float rs0[2] = {0.f, 0.f}, rs1[2] = {0.f, 0.f};
    #pragma unroll
    for (int mt = 0; mt < 2; mt++) {
        int q0 = qt*128 + wq + mt*16 + grp;
        #pragma unroll
        for (int nt = 0; nt < 4; nt++) {
            int kcol = kt*64 + wk + nt*8 + tig*2;
            float w0 = __expf(d[mt][nt][0] * SCALEF);
            float w1 = __expf(d[mt][nt][1] * SCALEF);
            float w2 = __expf(d[mt][nt][2] * SCALEF);
            float w3 = __expf(d[mt][nt][3] * SCALEF);
            rs0[mt] += w0 + w1;
            rs1[mt] += w2 + w3;
            *(float2*)&Sbase[(size_t)q0*512 + kcol]       = make_float2(w0, w1);
            *(float2*)&Sbase[(size_t)(q0+8)*512 + kcol]   = make_float2(w2, w3);
        }
        // reduce across tig lanes (same rows)
        rs0[mt] += __shfl_xor_sync(0xffffffffu, rs0[mt], 1);
        rs0[mt] += __shfl_xor_sync(0xffffffffu, rs0[mt], 2);
        rs1[mt] += __shfl_xor_sync(0xffffffffu, rs1[mt], 1);
        rs1[mt] += __shfl_xor_sync(0xffffffffu, rs1[mt], 2);
        if (tig == 0) {
            int slice = kt*2 + (w >> 2);
            g_lp[((size_t)(bh*16 + slice))*512 + q0]     = rs0[mt];
            g_lp[((size_t)(bh*16 + slice))*512 + q0 + 8] = rs1[mt];
        }
    }
}

// =========================================================================
// Kernel 5: pass2 + fused power-mean epilogue (round-8 proven; 16 partials).
// =========================================================================
__global__ __launch_bounds__(256, 1) void pass2_kernel() {
    __shared__ float As[32][68];
    __shared__ float Bs[32][36];
    __shared__ float sinvL[64];
    const int mt = blockIdx.x, bh = blockIdx.y;
    const int b = bh >> 3, h = bh & 7;
    const int tid = threadIdx.x, tx = tid & 15, ty = tid >> 4;
    const float* Ab = g_s  + (size_t)bh*512*512 + (size_t)mt*64*512;
    const float* Bb = g_vz + (size_t)bh*512*32;
    const int lm = tid & 63, lh = tid >> 6;
    const int bkr = tid >> 3, bcl = (tid & 7) * 4;

    if (tid < 64) {
        int q = mt*64 + tid;
        float L = 0.f;
        #pragma unroll
        for (int sl = 0; sl < 16; sl++) L += g_lp[((size_t)(bh*16 + sl))*512 + q];
        sinvL[tid] = 1.0f / L;
    }

    ull acc[2][2];
    acc[0][0] = acc[0][1] = acc[1][0] = acc[1][1] = 0ULL;

    float4 pa0 = *(const float4*)&Ab[(size_t)lm*512 + lh*8];
    float4 pa1 = *(const float4*)&Ab[(size_t)lm*512 + lh*8 + 4];
    float4 pb  = *(const float4*)&Bb[(size_t)bkr*32 + bcl];

    for (int k0 = 0; k0 < 512; k0 += 32) {
        {
            int c = lh*8;
            As[c+0][lm] = pa0.x; As[c+1][lm] = pa0.y;
            As[c+2][lm] = pa0.z; As[c+3][lm] = pa0.w;
            As[c+4][lm] = pa1.x; As[c+5][lm] = pa1.y;
            As[c+6][lm] = pa1.z; As[c+7][lm] = pa1.w;
        }
        *(float4*)&Bs[bkr][bcl] = pb;
        __syncthreads();
        if (k0 + 32 < 512) {
            pa0 = *(const float4*)&Ab[(size_t)lm*512 + k0 + 32 + lh*8];
            pa1 = *(const float4*)&Ab[(size_t)lm*512 + k0 + 32 + lh*8 + 4];
            pb  = *(const float4*)&Bb[(size_t)(k0 + 32 + bkr)*32 + bcl];
        }
        #pragma unroll
        for (int kk = 0; kk < 32; kk++) {
            ull a0 = *(const ull*)&As[kk][ty*4];
            ull a1 = *(const ull*)&As[kk][ty*4 + 2];
            float2 bf = *(const float2*)&Bs[kk][tx*2];
            ull b0 = f2pack(bf.x, bf.x), b1 = f2pack(bf.y, bf.y);
            acc[0][0] = f2fma(b0, a0, acc[0][0]); acc[0][1] = f2fma(b0, a1, acc[0][1]);
            acc[1][0] = f2fma(b1, a0, acc[1][0]); acc[1][1] = f2fma(b1, a1, acc[1][1]);
        }
        __syncthreads();
    }

    float v[2][4];
    f2unpack(acc[0][0], v[0][0], v[0][1]); f2unpack(acc[0][1], v[0][2], v[0][3]);
    f2unpack(acc[1][0], v[1][0], v[1][1]); f2unpack(acc[1][1], v[1][2], v[1][3]);

    const int a0 = h*32 + tx*2;
    const float ip0 = g_invp[a0],            ip1 = g_invp[a0+1];
    const float us0 = g_unscale[b*256 + a0], us1 = g_unscale[b*256 + a0 + 1];
    const float vm0 = g_vmin[b*256 + a0],    vm1 = g_vmin[b*256 + a0 + 1];
    #pragma unroll
    for (int r = 0; r < 4; r++) {
        int q = mt*64 + ty*4 + r;
        float il = sinvL[ty*4 + r];
        float e0 = __expf(__logf(v[0][r] * il) * ip0);
        float e1 = __expf(__logf(v[1][r] * il) * ip1);
        float2 o = make_float2((e0 - B_CONSTF) * us0 + vm0,
                               (e1 - B_CONSTF) * us1 + vm1);
        *(float2*)&g_e[(size_t)(b*512 + q)*256 + a0] = o;
    }
}

// =========================================================================
// Kernel 6: output projection (round-8 proven).
// =========================================================================
__global__ __launch_bounds__(256, 1) void out_gemm(const float* __restrict__ Wo,
                                                   float* __restrict__ out) {
    __shared__ float As[16][68];
    __shared__ float Bs[16][36];
    const int bn = blockIdx.x * 32;
    const int bm = blockIdx.y * 64;
    const int tid = threadIdx.x, tx = tid & 15, ty = tid >> 4;
    const int lm = tid >> 2, lc = tid & 3;
    const int ln = tid & 31, lk = tid >> 5;

    ull acc[2][2];
    acc[0][0] = acc[0][1] = acc[1][0] = acc[1][1] = 0ULL;

    float4 pa = *(const float4*)&g_e[(size_t)(bm + lm)*256 + lc*4];
    float4 pb;
    if (tid < 128) pb = *(const float4*)&Wo[(size_t)(bn + ln)*256 + lk*4];

    for (int k0 = 0; k0 < 256; k0 += 16) {
        As[lc*4+0][lm] = pa.x; As[lc*4+1][lm] = pa.y;
        As[lc*4+2][lm] = pa.z; As[lc*4+3][lm] = pa.w;
        if (tid < 128) {
            Bs[lk*4+0][ln] = pb.x; Bs[lk*4+1][ln] = pb.y;
            Bs[lk*4+2][ln] = pb.z; Bs[lk*4+3][ln] = pb.w;
        }
        __syncthreads();
        if (k0 + 16 < 256) {
            pa = *(const float4*)&g_e[(size_t)(bm + lm)*256 + k0 + 16 + lc*4];
            if (tid < 128) pb = *(const float4*)&Wo[(size_t)(bn + ln)*256 + k0 + 16 + lk*4];
        }
        #pragma unroll
        for (int kk = 0; kk < 16; kk++) {
            ull a0 = *(const ull*)&As[kk][ty*4];
            ull a1 = *(const ull*)&As[kk][ty*4+2];
            float2 bf = *(const float2*)&Bs[kk][tx*2];
            ull b0 = f2pack(bf.x, bf.x), b1 = f2pack(bf.y, bf.y);
            acc[0][0] = f2fma(b0, a0, acc[0][0]); acc[0][1] = f2fma(b0, a1, acc[0][1]);
            acc[1][0] = f2fma(b1, a0, acc[1][0]); acc[1][1] = f2fma(b1, a1, acc[1][1]);
        }
        __syncthreads();
    }
    float v[2][4];
    f2unpack(acc[0][0], v[0][0], v[0][1]); f2unpack(acc[0][1], v[0][2], v[0][3]);
    f2unpack(acc[1][0], v[1][0], v[1][1]); f2unpack(acc[1][1], v[1][2], v[1][3]);
    #pragma unroll
    for (int r = 0; r < 4; r++) {
        float2 o = make_float2(v[0][r], v[1][r]);
        *(float2*)&out[(size_t)(bm + ty*4 + r)*256 + bn + tx*2] = o;
    }
}

// ---------------- launch ----------------
extern "C" void kernel_launch(void* const* d_in, const int* in_sizes, int n_in,
                              void* d_out, int out_size) {
    const float* context = (const float*)d_in[0];
    const float* W_Q     = (const float*)d_in[1];
    const float* W_KV    = (const float*)d_in[2];
    const float* W_out   = (const float*)d_in[3];
    const float* p_param = (const float*)d_in[4];
    float* out = (float*)d_out;

    qkv_gemm    <<<dim3(12, 16),    256>>>(context, W_Q, W_KV);
    vstats_kernel<<<dim3(8, 2),     256>>>(p_param);
    vz_kernel   <<<dim3(8, 16),     256>>>();
    pass1_mma   <<<dim3(8, 4, 16),  256>>>();
    pass2_kernel<<<dim3(8, 16),     256>>>();
    out_gemm    <<<dim3(8, 16),     256>>>(W_out, out);
}

// round 13
// speedup vs baseline: 1.0263x; 1.0263x over previous
#include <cuda_runtime.h>
#include <cuda_bf16.h>
#include <math.h>

#define B_CONSTF 0.9f
#define EPSF 1e-10f
#define SCALEF 0.0625f

typedef unsigned long long ull;

// ---------------- device scratch ----------------
__device__ float g_qh[16*512*32];    // per-head Q   [bh][s][32]
__device__ float g_kh[16*512*32];    // per-head K   [bh][s][32]
__device__ float g_v [1024*256];     // V row-major  [b*s][256]
__device__ float g_vz[16*512*32];    // v_norm^p     [bh][s][32]
__device__ float g_s [16*512*512];   // exp scores   [bh][q][k]  (16.8MB)
__device__ float g_lp[16*16*512];    // row-sum partials [bh][kslice16][q]
__device__ float g_e [1024*256];     // power-mean result (row-major)
__device__ float g_vmin[512], g_nscale[512], g_unscale[512];
__device__ float g_p[256], g_invp[256];

// ---------------- f32x2 helpers (SIMT kernels) ----------------
__device__ __forceinline__ ull f2pack(float lo, float hi) {
    ull r; asm("mov.b64 %0, {%1, %2};" : "=l"(r) : "f"(lo), "f"(hi)); return r;
}
__device__ __forceinline__ void f2unpack(ull v, float& lo, float& hi) {
    asm("mov.b64 {%0, %1}, %2;" : "=f"(lo), "=f"(hi) : "l"(v));
}
__device__ __forceinline__ ull f2fma(ull a, ull b, ull c) {
    ull d; asm("fma.rn.f32x2 %0, %1, %2, %3;" : "=l"(d) : "l"(a), "l"(b), "l"(c)); return d;
}

// ---------------- warp mma helpers ----------------
__device__ __forceinline__ void mma_bf16(float* d, const unsigned* a, const unsigned* b) {
    asm volatile(
        "mma.sync.aligned.m16n8k16.row.col.f32.bf16.bf16.f32 "
        "{%0,%1,%2,%3}, {%4,%5,%6,%7}, {%8,%9}, {%0,%1,%2,%3};"
        : "+f"(d[0]), "+f"(d[1]), "+f"(d[2]), "+f"(d[3])
        : "r"(a[0]), "r"(a[1]), "r"(a[2]), "r"(a[3]), "r"(b[0]), "r"(b[1]));
}
__device__ __forceinline__ void ldsm_x4(unsigned& r0, unsigned& r1,
                                        unsigned& r2, unsigned& r3, unsigned addr) {
    asm volatile("ldmatrix.sync.aligned.m8n8.x4.shared.b16 {%0,%1,%2,%3}, [%4];"
        : "=r"(r0), "=r"(r1), "=r"(r2), "=r"(r3) : "r"(addr));
}
__device__ __forceinline__ unsigned smem_u32(const void* p) {
    unsigned r;
    asm("{ .reg .u64 t; cvta.to.shared.u64 t, %1; cvt.u32.u64 %0, t; }" : "=r"(r) : "l"(p));
    return r;
}
// fp32 -> (hi,lo) bf16x2 words
__device__ __forceinline__ void split2(float x0, float x1, unsigned& hw, unsigned& lw) {
    __nv_bfloat16 h0 = __float2bfloat16(x0);
    __nv_bfloat16 h1 = __float2bfloat16(x1);
    __nv_bfloat16 l0 = __float2bfloat16(x0 - __bfloat162float(h0));
    __nv_bfloat16 l1 = __float2bfloat16(x1 - __bfloat162float(h1));
    hw = (unsigned)__bfloat16_as_ushort(h0) | ((unsigned)__bfloat16_as_ushort(h1) << 16);
    lw = (unsigned)__bfloat16_as_ushort(l0) | ((unsigned)__bfloat16_as_ushort(l1) << 16);
}

// =========================================================================
// Kernel 1: fused QKV projection (round-8 proven).
// =========================================================================
__global__ __launch_bounds__(256) void qkv_gemm(
    const float* __restrict__ ctx, const float* __restrict__ W_Q,
    const float* __restrict__ W_KV)
{
    __shared__ float As[16][68];
    __shared__ float Bs[16][68];
    const int tid = threadIdx.x;
    const int tx = tid & 15, ty = tid >> 4;
    const int bm = blockIdx.y * 64;
    const int bn = blockIdx.x * 64;
    const float* Bsrc = (bn < 256) ? (W_Q + (size_t)bn * 256)
                                   : (W_KV + (size_t)(bn - 256) * 256);
    const int lm = tid >> 2, lc = tid & 3;

    ull acc[4][2];
    #pragma unroll
    for (int n = 0; n < 4; n++) { acc[n][0] = 0ULL; acc[n][1] = 0ULL; }

    float4 pa = *(const float4*)&ctx [(size_t)(bm + lm) * 256 + lc*4];
    float4 pb = *(const float4*)&Bsrc[(size_t)lm * 256 + lc*4];

    for (int k0 = 0; k0 < 256; k0 += 16) {
        As[lc*4+0][lm] = pa.x; As[lc*4+1][lm] = pa.y;
        As[lc*4+2][lm] = pa.z; As[lc*4+3][lm] = pa.w;
        Bs[lc*4+0][lm] = pb.x; Bs[lc*4+1][lm] = pb.y;
        Bs[lc*4+2][lm] = pb.z; Bs[lc*4+3][lm] = pb.w;
        __syncthreads();
        if (k0 + 16 < 256) {
            pa = *(const float4*)&ctx [(size_t)(bm + lm) * 256 + k0 + 16 + lc*4];
            pb = *(const float4*)&Bsrc[(size_t)lm * 256 + k0 + 16 + lc*4];
        }
        #pragma unroll
        for (int kk = 0; kk < 16; kk++) {
            ull a0 = *(const ull*)&As[kk][ty*4];
            ull a1 = *(const ull*)&As[kk][ty*4+2];
            float4 bf = *(const float4*)&Bs[kk][tx*4];
            ull b0 = f2pack(bf.x, bf.x), b1 = f2pack(bf.y, bf.y);
            ull b2 = f2pack(bf.z, bf.z), b3 = f2pack(bf.w, bf.w);
            acc[0][0] = f2fma(b0, a0, acc[0][0]); acc[0][1] = f2fma(b0, a1, acc[0][1]);
            acc[1][0] = f2fma(b1, a0, acc[1][0]); acc[1][1] = f2fma(b1, a1, acc[1][1]);
            acc[2][0] = f2fma(b2, a0, acc[2][0]); acc[2][1] = f2fma(b2, a1, acc[2][1]);
            acc[3][0] = f2fma(b3, a0, acc[3][0]); acc[3][1] = f2fma(b3, a1, acc[3][1]);
        }
        __syncthreads();
    }

    float v[4][4];
    #pragma unroll
    for (int n = 0; n < 4; n++) {
        f2unpack(acc[n][0], v[n][0], v[n][1]);
        f2unpack(acc[n][1], v[n][2], v[n][3]);
    }
    const int c = bn + tx*4;
    #pragma unroll
    for (int r = 0; r < 4; r++) {
        int row = bm + ty*4 + r;
        float4 o = make_float4(v[0][r], v[1][r], v[2][r], v[3][r]);
        int b = row >> 9, s = row & 511;
        if (c < 256) {
            int h = c >> 5, a = c & 31;
            *(float4*)&g_qh[((size_t)((b*8+h)*512 + s))*32 + a] = o;
        } else if (c < 512) {
            int kc = c - 256, h = kc >> 5, a = kc & 31;
            *(float4*)&g_kh[((size_t)((b*8+h)*512 + s))*32 + a] = o;
        } else {
            *(float4*)&g_v[(size_t)row * 256 + (c - 512)] = o;
        }
    }
}

// =========================================================================
// Kernel 2: v min/max per (b,d) + p/invp.
// =========================================================================
__global__ __launch_bounds__(256) void vstats_kernel(const float* __restrict__ p_param) {
    __shared__ float smn[8][32], smx[8][32];
    const int b = blockIdx.y, dc = blockIdx.x;
    const int dd = threadIdx.x & 31, sl = threadIdx.x >> 5;
    const int d = dc*32 + dd;
    float mn = 1e30f, mx = -1e30f;
    const float* base = g_v + (size_t)(b*512 + sl*64) * 256 + d;
    #pragma unroll 4
    for (int i = 0; i < 64; i++) {
        float v = base[(size_t)i * 256];
        mn = fminf(mn, v); mx = fmaxf(mx, v);
    }
    smn[sl][dd] = mn; smx[sl][dd] = mx;
    __syncthreads();
    if (sl == 0) {
        #pragma unroll
        for (int t = 1; t < 8; t++) {
            mn = fminf(mn, smn[t][dd]); mx = fmaxf(mx, smx[t][dd]);
        }
        float range = mx - mn + EPSF;
        g_vmin   [b*256 + d] = mn;
        g_nscale [b*256 + d] = (1.0f - B_CONSTF) / range;
        g_unscale[b*256 + d] = range / (1.0f - B_CONSTF);
        if (b == 0) {
            float pp = p_param[d];
            float p  = 50000.0f * tanhf(0.005f * pp) + 1.0f;
            if (p == 0.0f) p = 1e-4f;
            g_p[d] = p; g_invp[d] = 1.0f / p;
        }
    }
}

// =========================================================================
// Kernel 3: vz = v_norm^p per-head.
// =========================================================================
__global__ __launch_bounds__(256) void vz_kernel() {
    __shared__ float s_p[32], s_ns[32], s_vm[32];
    const int bh = blockIdx.y, sc = blockIdx.x;
    const int b = bh >> 3, h = bh & 7;
    const int tid = threadIdx.x;
    if (tid < 32) {
        int d = h*32 + tid;
        s_p[tid]  = g_p[d];
        s_ns[tid] = g_nscale[b*256 + d];
        s_vm[tid] = g_vmin[b*256 + d];
    }
    __syncthreads();
    const int a = tid & 31, sq = tid >> 5;
    #pragma unroll
    for (int it = 0; it < 8; it++) {
        int s = sc*64 + it*8 + sq;
        float v  = g_v[(size_t)(b*512 + s) * 256 + h*32 + a];
        float vn = (v - s_vm[a]) * s_ns[a] + B_CONSTF;
        g_vz[((size_t)(bh*512 + s))*32 + a] = __expf(s_p[a] * __logf(vn));
    }
}

// =========================================================================
// Kernel 4: pass1, warp MMA + ldmatrix feed (split-bf16, fp32 accum).
// grid (8 kt, 4 qt, 16 bh) = 512 blocks, 256 thr (8 warps).
// Tile 128q x 64k, K=32. Warp w: q-chunk (w&3)*32, k-chunk (w>>2)*32.
// S = Qh*Kh^T + Ql*Kh^T + Qh*Kl^T.
// PSW=20 words (80B row stride) -> ldmatrix conflict-free.
// =========================================================================
#define PSW 20

__global__ __launch_bounds__(256, 1) void pass1_mma() {
    __shared__ unsigned Qhi[128*PSW], Qlo[128*PSW];
    __shared__ unsigned Khi[64*PSW],  Klo[64*PSW];
    const int tid = threadIdx.x, lane = tid & 31, w = tid >> 5;
    const int kt = blockIdx.x, qt = blockIdx.y, bh = blockIdx.z;
    const int tig = lane & 3, grp = lane >> 2;

    // ---- fill Q: 128 rows x 32 cols, thread -> (row = tid>>1, half = tid&1)
    {
        int row = tid >> 1, half = tid & 1;
        const float* src = g_qh + ((size_t)bh*512 + qt*128 + row)*32 + half*16;
        #pragma unroll
        for (int j = 0; j < 8; j++) {
            unsigned hw, lw;
            split2(src[2*j], src[2*j+1], hw, lw);
            Qhi[row*PSW + half*8 + j] = hw;
            Qlo[row*PSW + half*8 + j] = lw;
        }
    }
    // ---- fill K: 64 rows x 32 cols (threads 0..127)
    if (tid < 128) {
        int row = tid >> 1, half = tid & 1;
        const float* src = g_kh + ((size_t)bh*512 + kt*64 + row)*32 + half*16;
        #pragma unroll
        for (int j = 0; j < 8; j++) {
            unsigned hw, lw;
            split2(src[2*j], src[2*j+1], hw, lw);
            Khi[row*PSW + half*8 + j] = hw;
            Klo[row*PSW + half*8 + j] = lw;
        }
    }
    __syncthreads();

    const int wq = (w & 3) * 32;   // q offset in tile
    const int wk = (w >> 2) * 32;  // k offset in tile

    const unsigned qhiB = smem_u32(Qhi), qloB = smem_u32(Qlo);
    const unsigned khiB = smem_u32(Khi), kloB = smem_u32(Klo);

    // ---- B fragments via ldmatrix.x4 (nt-pair per load): [nt][kc][2]
    unsigned bfh[4][2][2], bfl[4][2][2];
    {
        // lane -> (row, koff) within an x4 covering nt pair {np*2, np*2+1}
        #pragma unroll
        for (int np = 0; np < 2; np++) {
            unsigned rowoff = (unsigned)((wk + np*16 + ((lane >> 4) & 1)*8 + (lane & 7)) * (PSW*4))
                            + ((lane >> 3) & 1) * 16;
            #pragma unroll
            for (int kc = 0; kc < 2; kc++) {
                unsigned m0, m1, m2, m3;
                ldsm_x4(m0, m1, m2, m3, khiB + rowoff + kc*32);
                bfh[np*2][kc][0] = m0; bfh[np*2][kc][1] = m1;
                bfh[np*2+1][kc][0] = m2; bfh[np*2+1][kc][1] = m3;
                ldsm_x4(m0, m1, m2, m3, kloB + rowoff + kc*32);
                bfl[np*2][kc][0] = m0; bfl[np*2][kc][1] = m1;
                bfl[np*2+1][kc][0] = m2; bfl[np*2+1][kc][1] = m3;
            }
        }
    }

    float* Sbase = g_s + (size_t)bh*512*512;

    #pragma unroll
    for (int mt = 0; mt < 2; mt++) {
        // A fragments via ldmatrix.x4: [hilo][kc][4]
        unsigned ah[2][4], al[2][4];
        {
            unsigned rowoff = (unsigned)((wq + mt*16 + (lane & 15)) * (PSW*4))
                            + ((lane >> 4) & 1) * 16;
            #pragma unroll
            for (int kc = 0; kc < 2; kc++) {
                ldsm_x4(ah[kc][0], ah[kc][1], ah[kc][2], ah[kc][3], qhiB + rowoff + kc*32);
                ldsm_x4(al[kc][0], al[kc][1], al[kc][2], al[kc][3], qloB + rowoff + kc*32);
            }
        }

        float d[4][4];
        #pragma unroll
        for (int nt = 0; nt < 4; nt++)
            #pragma unroll
            for (int i = 0; i < 4; i++) d[nt][i] = 0.f;

        #pragma unroll
        for (int nt = 0; nt < 4; nt++) {
            #pragma unroll
            for (int kc = 0; kc < 2; kc++) {
                mma_bf16(d[nt], ah[kc], bfh[nt][kc]);   // hi*hi
                mma_bf16(d[nt], al[kc], bfh[nt][kc]);   // lo*hi
                mma_bf16(d[nt], ah[kc], bfl[nt][kc]);   // hi*lo
            }
        }

        // ---- epilogue: exp, store, rowsum partials
        int q0 = qt*128 + wq + mt*16 + grp;
        float rs0 = 0.f, rs1 = 0.f;
        #pragma unroll
        for (int nt = 0; nt < 4; nt++) {
            int kcol = kt*64 + wk + nt*8 + tig*2;
            float w0 = __expf(d[nt][0] * SCALEF);
            float w1 = __expf(d[nt][1] * SCALEF);
            float w2 = __expf(d[nt][2] * SCALEF);
            float w3 = __expf(d[nt][3] * SCALEF);
            rs0 += w0 + w1;
            rs1 += w2 + w3;
            *(float2*)&Sbase[(size_t)q0*512 + kcol]     = make_float2(w0, w1);
            *(float2*)&Sbase[(size_t)(q0+8)*512 + kcol] = make_float2(w2, w3);
        }
        rs0 += __shfl_xor_sync(0xffffffffu, rs0, 1);
        rs0 += __shfl_xor_sync(0xffffffffu, rs0, 2);
        rs1 += __shfl_xor_sync(0xffffffffu, rs1, 1);
        rs1 += __shfl_xor_sync(0xffffffffu, rs1, 2);
        if (tig == 0) {
            int slice = kt*2 + (w >> 2);
            g_lp[((size_t)(bh*16 + slice))*512 + q0]     = rs0;
            g_lp[((size_t)(bh*16 + slice))*512 + q0 + 8] = rs1;
        }
    }
}

// =========================================================================
// Kernel 5: pass2 + fused power-mean epilogue (round-8 proven; 16 partials).
// =========================================================================
__global__ __launch_bounds__(256, 1) void pass2_kernel() {
    __shared__ float As[32][68];
    __shared__ float Bs[32][36];
    __shared__ float sinvL[64];
    const int mt = blockIdx.x, bh = blockIdx.y;
    const int b = bh >> 3, h = bh & 7;
    const int tid = threadIdx.x, tx = tid & 15, ty = tid >> 4;
    const float* Ab = g_s  + (size_t)bh*512*512 + (size_t)mt*64*512;
    const float* Bb = g_vz + (size_t)bh*512*32;
    const int lm = tid & 63, lh = tid >> 6;
    const int bkr = tid >> 3, bcl = (tid & 7) * 4;

    if (tid < 64) {
        int q = mt*64 + tid;
        float L = 0.f;
        #pragma unroll
        for (int sl = 0; sl < 16; sl++) L += g_lp[((size_t)(bh*16 + sl))*512 + q];
        sinvL[tid] = 1.0f / L;
    }

    ull acc[2][2];
    acc[0][0] = acc[0][1] = acc[1][0] = acc[1][1] = 0ULL;

    float4 pa0 = *(const float4*)&Ab[(size_t)lm*512 + lh*8];
    float4 pa1 = *(const float4*)&Ab[(size_t)lm*512 + lh*8 + 4];
    float4 pb  = *(const float4*)&Bb[(size_t)bkr*32 + bcl];

    for (int k0 = 0; k0 < 512; k0 += 32) {
        {
            int c = lh*8;
            As[c+0][lm] = pa0.x; As[c+1][lm] = pa0.y;
            As[c+2][lm] = pa0.z; As[c+3][lm] = pa0.w;
            As[c+4][lm] = pa1.x; As[c+5][lm] = pa1.y;
            As[c+6][lm] = pa1.z; As[c+7][lm] = pa1.w;
        }
        *(float4*)&Bs[bkr][bcl] = pb;
        __syncthreads();
        if (k0 + 32 < 512) {
            pa0 = *(const float4*)&Ab[(size_t)lm*512 + k0 + 32 + lh*8];
            pa1 = *(const float4*)&Ab[(size_t)lm*512 + k0 + 32 + lh*8 + 4];
            pb  = *(const float4*)&Bb[(size_t)(k0 + 32 + bkr)*32 + bcl];
        }
        #pragma unroll
        for (int kk = 0; kk < 32; kk++) {
            ull a0 = *(const ull*)&As[kk][ty*4];
            ull a1 = *(const ull*)&As[kk][ty*4 + 2];
            float2 bf = *(const float2*)&Bs[kk][tx*2];
            ull b0 = f2pack(bf.x, bf.x), b1 = f2pack(bf.y, bf.y);
            acc[0][0] = f2fma(b0, a0, acc[0][0]); acc[0][1] = f2fma(b0, a1, acc[0][1]);
            acc[1][0] = f2fma(b1, a0, acc[1][0]); acc[1][1] = f2fma(b1, a1, acc[1][1]);
        }
        __syncthreads();
    }

    float v[2][4];
    f2unpack(acc[0][0], v[0][0], v[0][1]); f2unpack(acc[0][1], v[0][2], v[0][3]);
    f2unpack(acc[1][0], v[1][0], v[1][1]); f2unpack(acc[1][1], v[1][2], v[1][3]);

    const int a0 = h*32 + tx*2;
    const float ip0 = g_invp[a0],            ip1 = g_invp[a0+1];
    const float us0 = g_unscale[b*256 + a0], us1 = g_unscale[b*256 + a0 + 1];
    const float vm0 = g_vmin[b*256 + a0],    vm1 = g_vmin[b*256 + a0 + 1];
    #pragma unroll
    for (int r = 0; r < 4; r++) {
        int q = mt*64 + ty*4 + r;
        float il = sinvL[ty*4 + r];
        float e0 = __expf(__logf(v[0][r] * il) * ip0);
        float e1 = __expf(__logf(v[1][r] * il) * ip1);
        float2 o = make_float2((e0 - B_CONSTF) * us0 + vm0,
                               (e1 - B_CONSTF) * us1 + vm1);
        *(float2*)&g_e[(size_t)(b*512 + q)*256 + a0] = o;
    }
}

// =========================================================================
// Kernel 6: output projection (round-8 proven).
// =========================================================================
__global__ __launch_bounds__(256, 1) void out_gemm(const float* __restrict__ Wo,
                                                   float* __restrict__ out) {
    __shared__ float As[16][68];
    __shared__ float Bs[16][36];
    const int bn = blockIdx.x * 32;
    const int bm = blockIdx.y * 64;
    const int tid = threadIdx.x, tx = tid & 15, ty = tid >> 4;
    const int lm = tid >> 2, lc = tid & 3;
    const int ln = tid & 31, lk = tid >> 5;

    ull acc[2][2];
    acc[0][0] = acc[0][1] = acc[1][0] = acc[1][1] = 0ULL;

    float4 pa = *(const float4*)&g_e[(size_t)(bm + lm)*256 + lc*4];
    float4 pb;
    if (tid < 128) pb = *(const float4*)&Wo[(size_t)(bn + ln)*256 + lk*4];

    for (int k0 = 0; k0 < 256; k0 += 16) {
        As[lc*4+0][lm] = pa.x; As[lc*4+1][lm] = pa.y;
        As[lc*4+2][lm] = pa.z; As[lc*4+3][lm] = pa.w;
        if (tid < 128) {
            Bs[lk*4+0][ln] = pb.x; Bs[lk*4+1][ln] = pb.y;
            Bs[lk*4+2][ln] = pb.z; Bs[lk*4+3][ln] = pb.w;
        }
        __syncthreads();
        if (k0 + 16 < 256) {
            pa = *(const float4*)&g_e[(size_t)(bm + lm)*256 + k0 + 16 + lc*4];
            if (tid < 128) pb = *(const float4*)&Wo[(size_t)(bn + ln)*256 + k0 + 16 + lk*4];
        }
        #pragma unroll
        for (int kk = 0; kk < 16; kk++) {
            ull a0 = *(const ull*)&As[kk][ty*4];
            ull a1 = *(const ull*)&As[kk][ty*4+2];
            float2 bf = *(const float2*)&Bs[kk][tx*2];
            ull b0 = f2pack(bf.x, bf.x), b1 = f2pack(bf.y, bf.y);
            acc[0][0] = f2fma(b0, a0, acc[0][0]); acc[0][1] = f2fma(b0, a1, acc[0][1]);
            acc[1][0] = f2fma(b1, a0, acc[1][0]); acc[1][1] = f2fma(b1, a1, acc[1][1]);
        }
        __syncthreads();
    }
    float v[2][4];
    f2unpack(acc[0][0], v[0][0], v[0][1]); f2unpack(acc[0][1], v[0][2], v[0][3]);
    f2unpack(acc[1][0], v[1][0], v[1][1]); f2unpack(acc[1][1], v[1][2], v[1][3]);
    #pragma unroll
    for (int r = 0; r < 4; r++) {
        float2 o = make_float2(v[0][r], v[1][r]);
        *(float2*)&out[(size_t)(bm + ty*4 + r)*256 + bn + tx*2] = o;
    }
}

// ---------------- launch ----------------
extern "C" void kernel_launch(void* const* d_in, const int* in_sizes, int n_in,
                              void* d_out, int out_size) {
    const float* context = (const float*)d_in[0];
    const float* W_Q     = (const float*)d_in[1];
    const float* W_KV    = (const float*)d_in[2];
    const float* W_out   = (const float*)d_in[3];
    const float* p_param = (const float*)d_in[4];
    float* out = (float*)d_out;

    qkv_gemm    <<<dim3(12, 16),    256>>>(context, W_Q, W_KV);
    vstats_kernel<<<dim3(8, 2),     256>>>(p_param);
    vz_kernel   <<<dim3(8, 16),     256>>>();
    pass1_mma   <<<dim3(8, 4, 16),  256>>>();
    pass2_kernel<<<dim3(8, 16),     256>>>();
    out_gemm    <<<dim3(8, 16),     256>>>(W_out, out);
}

// round 16
// speedup vs baseline: 1.1853x; 1.1549x over previous
#include <cuda_runtime.h>
#include <cuda_bf16.h>
#include <math.h>

#define B_CONSTF 0.9f
#define EPSF 1e-10f
#define SCALEF 0.0625f

typedef unsigned long long ull;

// ---------------- device scratch ----------------
__device__ float g_qh[16*512*32];    // per-head Q   [bh][s][32]
__device__ float g_kh[16*512*32];    // per-head K   [bh][s][32]
__device__ float g_v [1024*256];     // V row-major  [b*s][256]
__device__ float g_vz[16*512*32];    // v_norm^p     [bh][s][32]
__device__ float g_e [1024*256];     // power-mean result (row-major)
__device__ float g_vmin[512], g_nscale[512], g_unscale[512];
__device__ float g_p[256], g_invp[256];

// ---------------- f32x2 helpers ----------------
__device__ __forceinline__ ull f2pack(float lo, float hi) {
    ull r; asm("mov.b64 %0, {%1, %2};" : "=l"(r) : "f"(lo), "f"(hi)); return r;
}
__device__ __forceinline__ void f2unpack(ull v, float& lo, float& hi) {
    asm("mov.b64 {%0, %1}, %2;" : "=f"(lo), "=f"(hi) : "l"(v));
}
__device__ __forceinline__ ull f2fma(ull a, ull b, ull c) {
    ull d; asm("fma.rn.f32x2 %0, %1, %2, %3;" : "=l"(d) : "l"(a), "l"(b), "l"(c)); return d;
}

// ---------------- warp mma helpers ----------------
__device__ __forceinline__ void mma_bf16(float* d, const unsigned* a, const unsigned* b) {
    asm volatile(
        "mma.sync.aligned.m16n8k16.row.col.f32.bf16.bf16.f32 "
        "{%0,%1,%2,%3}, {%4,%5,%6,%7}, {%8,%9}, {%0,%1,%2,%3};"
        : "+f"(d[0]), "+f"(d[1]), "+f"(d[2]), "+f"(d[3])
        : "r"(a[0]), "r"(a[1]), "r"(a[2]), "r"(a[3]), "r"(b[0]), "r"(b[1]));
}
// fp32 -> (hi,lo) bf16x2 words (2-way split)
__device__ __forceinline__ void split2(float x0, float x1, unsigned& hw, unsigned& lw) {
    __nv_bfloat16 h0 = __float2bfloat16(x0);
    __nv_bfloat16 h1 = __float2bfloat16(x1);
    __nv_bfloat16 l0 = __float2bfloat16(x0 - __bfloat162float(h0));
    __nv_bfloat16 l1 = __float2bfloat16(x1 - __bfloat162float(h1));
    hw = (unsigned)__bfloat16_as_ushort(h0) | ((unsigned)__bfloat16_as_ushort(h1) << 16);
    lw = (unsigned)__bfloat16_as_ushort(l0) | ((unsigned)__bfloat16_as_ushort(l1) << 16);
}

// =========================================================================
// Kernel 1: fused QKV projection (round-8 proven).
// =========================================================================
__global__ __launch_bounds__(256) void qkv_gemm(
    const float* __restrict__ ctx, const float* __restrict__ W_Q,
    const float* __restrict__ W_KV)
{
    __shared__ float As[16][68];
    __shared__ float Bs[16][68];
    const int tid = threadIdx.x;
    const int tx = tid & 15, ty = tid >> 4;
    const int bm = blockIdx.y * 64;
    const int bn = blockIdx.x * 64;
    const float* Bsrc = (bn < 256) ? (W_Q + (size_t)bn * 256)
                                   : (W_KV + (size_t)(bn - 256) * 256);
    const int lm = tid >> 2, lc = tid & 3;

    ull acc[4][2];
    #pragma unroll
    for (int n = 0; n < 4; n++) { acc[n][0] = 0ULL; acc[n][1] = 0ULL; }

    float4 pa = *(const float4*)&ctx [(size_t)(bm + lm) * 256 + lc*4];
    float4 pb = *(const float4*)&Bsrc[(size_t)lm * 256 + lc*4];

    for (int k0 = 0; k0 < 256; k0 += 16) {
        As[lc*4+0][lm] = pa.x; As[lc*4+1][lm] = pa.y;
        As[lc*4+2][lm] = pa.z; As[lc*4+3][lm] = pa.w;
        Bs[lc*4+0][lm] = pb.x; Bs[lc*4+1][lm] = pb.y;
        Bs[lc*4+2][lm] = pb.z; Bs[lc*4+3][lm] = pb.w;
        __syncthreads();
        if (k0 + 16 < 256) {
            pa = *(const float4*)&ctx [(size_t)(bm + lm) * 256 + k0 + 16 + lc*4];
            pb = *(const float4*)&Bsrc[(size_t)lm * 256 + k0 + 16 + lc*4];
        }
        #pragma unroll
        for (int kk = 0; kk < 16; kk++) {
            ull a0 = *(const ull*)&As[kk][ty*4];
            ull a1 = *(const ull*)&As[kk][ty*4+2];
            float4 bf = *(const float4*)&Bs[kk][tx*4];
            ull b0 = f2pack(bf.x, bf.x), b1 = f2pack(bf.y, bf.y);
            ull b2 = f2pack(bf.z, bf.z), b3 = f2pack(bf.w, bf.w);
            acc[0][0] = f2fma(b0, a0, acc[0][0]); acc[0][1] = f2fma(b0, a1, acc[0][1]);
            acc[1][0] = f2fma(b1, a0, acc[1][0]); acc[1][1] = f2fma(b1, a1, acc[1][1]);
            acc[2][0] = f2fma(b2, a0, acc[2][0]); acc[2][1] = f2fma(b2, a1, acc[2][1]);
            acc[3][0] = f2fma(b3, a0, acc[3][0]); acc[3][1] = f2fma(b3, a1, acc[3][1]);
        }
        __syncthreads();
    }

    float v[4][4];
    #pragma unroll
    for (int n = 0; n < 4; n++) {
        f2unpack(acc[n][0], v[n][0], v[n][1]);
        f2unpack(acc[n][1], v[n][2], v[n][3]);
    }
    const int c = bn + tx*4;
    #pragma unroll
    for (int r = 0; r < 4; r++) {
        int row = bm + ty*4 + r;
        float4 o = make_float4(v[0][r], v[1][r], v[2][r], v[3][r]);
        int b = row >> 9, s = row & 511;
        if (c < 256) {
            int h = c >> 5, a = c & 31;
            *(float4*)&g_qh[((size_t)((b*8+h)*512 + s))*32 + a] = o;
        } else if (c < 512) {
            int kc = c - 256, h = kc >> 5, a = kc & 31;
            *(float4*)&g_kh[((size_t)((b*8+h)*512 + s))*32 + a] = o;
        } else {
            *(float4*)&g_v[(size_t)row * 256 + (c - 512)] = o;
        }
    }
}

// =========================================================================
// Kernel 2: v min/max per (b,d) + p/invp.
// =========================================================================
__global__ __launch_bounds__(256) void vstats_kernel(const float* __restrict__ p_param) {
    __shared__ float smn[8][32], smx[8][32];
    const int b = blockIdx.y, dc = blockIdx.x;
    const int dd = threadIdx.x & 31, sl = threadIdx.x >> 5;
    const int d = dc*32 + dd;
    float mn = 1e30f, mx = -1e30f;
    const float* base = g_v + (size_t)(b*512 + sl*64) * 256 + d;
    #pragma unroll 4
    for (int i = 0; i < 64; i++) {
        float v = base[(size_t)i * 256];
        mn = fminf(mn, v); mx = fmaxf(mx, v);
    }
    smn[sl][dd] = mn; smx[sl][dd] = mx;
    __syncthreads();
    if (sl == 0) {
        #pragma unroll
        for (int t = 1; t < 8; t++) {
            mn = fminf(mn, smn[t][dd]); mx = fmaxf(mx, smx[t][dd]);
        }
        float range = mx - mn + EPSF;
        g_vmin   [b*256 + d] = mn;
        g_nscale [b*256 + d] = (1.0f - B_CONSTF) / range;
        g_unscale[b*256 + d] = range / (1.0f - B_CONSTF);
        if (b == 0) {
            float pp = p_param[d];
            float p  = 50000.0f * tanhf(0.005f * pp) + 1.0f;
            if (p == 0.0f) p = 1e-4f;
            g_p[d] = p; g_invp[d] = 1.0f / p;
        }
    }
}

// =========================================================================
// Kernel 3: vz = v_norm^p per-head.
// =========================================================================
__global__ __launch_bounds__(256) void vz_kernel() {
    __shared__ float s_p[32], s_ns[32], s_vm[32];
    const int bh = blockIdx.y, sc = blockIdx.x;
    const int b = bh >> 3, h = bh & 7;
    const int tid = threadIdx.x;
    if (tid < 32) {
        int d = h*32 + tid;
        s_p[tid]  = g_p[d];
        s_ns[tid] = g_nscale[b*256 + d];
        s_vm[tid] = g_vmin[b*256 + d];
    }
    __syncthreads();
    const int a = tid & 31, sq = tid >> 5;
    #pragma unroll
    for (int it = 0; it < 8; it++) {
        int s = sc*64 + it*8 + sq;
        float v  = g_v[(size_t)(b*512 + s) * 256 + h*32 + a];
        float vn = (v - s_vm[a]) * s_ns[a] + B_CONSTF;
        g_vz[((size_t)(bh*512 + s))*32 + a] = __expf(s_p[a] * __logf(vn));
    }
}

// =========================================================================
// Kernel 4: FUSED attention, proven numerics:
//   S chunk: tensor-core split-bf16 (3-term, as passing rounds 12/13)
//   exp fp32 -> Ss staged TRANSPOSED in smem (no GMEM round trip)
//   PV: pass2's exact fp32 f2fma loop over Ss chunk
// grid (8 qt, 16 bh) = 128 blocks, 256 thr (8 warps).
// Chunk loop: 8 x 64 keys. Warp w (S phase): mq = w&3 (16 q), kh = w>>2 (32 k).
// PV phase: pass2 mapping tx=tid&15 (2 feats), ty=tid>>4 (4 q rows).
// =========================================================================
#define PW 20   // K/Q tile row stride in words (80B)

__global__ __launch_bounds__(256, 1) void attn_fused() {
    __shared__ unsigned Qhi[64*PW], Qlo[64*PW];   // 64 q x 32 feat (split)
    __shared__ unsigned Khi[64*PW], Klo[64*PW];   // 64 keys x 32 feat (split)
    __shared__ float Ss[64][66];                  // [key][q] exp'd scores (fp32)
    __shared__ float Vzs[64][36];                 // [key][feat] fp32
    __shared__ float Lbuf[2][64];
    __shared__ float sinvL[64];

    const int tid = threadIdx.x, lane = tid & 31, w = tid >> 5;
    const int tig = lane & 3, grp = lane >> 2;
    const int qt = blockIdx.x, bh = blockIdx.y;
    const int b = bh >> 3, h = bh & 7;
    const int mq = w & 3, kh = w >> 2;
    const int tx = tid & 15, ty = tid >> 4;

    // ---- Q fill: row = tid>>2, part = tid&3 (8 floats each)
    {
        int row = tid >> 2, part = tid & 3;
        const float* src = g_qh + ((size_t)bh*512 + qt*64 + row)*32 + part*8;
        float4 x0 = *(const float4*)&src[0];
        float4 x1 = *(const float4*)&src[4];
        unsigned hw, lw;
        split2(x0.x, x0.y, hw, lw); Qhi[row*PW + part*4 + 0] = hw; Qlo[row*PW + part*4 + 0] = lw;
        split2(x0.z, x0.w, hw, lw); Qhi[row*PW + part*4 + 1] = hw; Qlo[row*PW + part*4 + 1] = lw;
        split2(x1.x, x1.y, hw, lw); Qhi[row*PW + part*4 + 2] = hw; Qlo[row*PW + part*4 + 2] = lw;
        split2(x1.z, x1.w, hw, lw); Qhi[row*PW + part*4 + 3] = hw; Qlo[row*PW + part*4 + 3] = lw;
    }
    __syncthreads();

    // ---- Q fragments (once per warp, depend on mq only)
    unsigned ah[2][4], al[2][4];
    {
        int r0 = (mq*16 + grp) * PW, r1 = r0 + 8*PW;
        #pragma unroll
        for (int kc = 0; kc < 2; kc++) {
            int o = kc*8 + tig;
            ah[kc][0] = Qhi[r0 + o];     ah[kc][1] = Qhi[r1 + o];
            ah[kc][2] = Qhi[r0 + o + 4]; ah[kc][3] = Qhi[r1 + o + 4];
            al[kc][0] = Qlo[r0 + o];     al[kc][1] = Qlo[r1 + o];
            al[kc][2] = Qlo[r0 + o + 4]; al[kc][3] = Qlo[r1 + o + 4];
        }
    }

    ull acc[2][2];   // PV accumulators (pass2-style, fp32x2)
    acc[0][0] = acc[0][1] = acc[1][0] = acc[1][1] = 0ULL;
    float rs0 = 0.f, rs1 = 0.f;

    for (int it = 0; it < 8; it++) {
        // ---- fill K chunk (64 keys x 32 feat, split) + Vzs chunk (fp32)
        {
            int row = tid >> 2, part = tid & 3;
            const float* src = g_kh + ((size_t)bh*512 + it*64 + row)*32 + part*8;
            float4 x0 = *(const float4*)&src[0];
            float4 x1 = *(const float4*)&src[4];
            unsigned hw, lw;
            split2(x0.x, x0.y, hw, lw); Khi[row*PW + part*4 + 0] = hw; Klo[row*PW + part*4 + 0] = lw;
            split2(x0.z, x0.w, hw, lw); Khi[row*PW + part*4 + 1] = hw; Klo[row*PW + part*4 + 1] = lw;
            split2(x1.x, x1.y, hw, lw); Khi[row*PW + part*4 + 2] = hw; Klo[row*PW + part*4 + 2] = lw;
            split2(x1.z, x1.w, hw, lw); Khi[row*PW + part*4 + 3] = hw; Klo[row*PW + part*4 + 3] = lw;

            const float* vs = g_vz + ((size_t)bh*512 + it*64 + row)*32 + part*8;
            *(float4*)&Vzs[row][part*8]     = *(const float4*)&vs[0];
            *(float4*)&Vzs[row][part*8 + 4] = *(const float4*)&vs[4];
        }
        __syncthreads();

        // ---- S: warp computes 16q x 32k (split-bf16, 3 terms — proven)
        float d[4][4];
        #pragma unroll
        for (int n = 0; n < 4; n++)
            #pragma unroll
            for (int i = 0; i < 4; i++) d[n][i] = 0.f;

        #pragma unroll
        for (int nt = 0; nt < 4; nt++) {
            int nb = (kh*32 + nt*8 + grp) * PW;
            #pragma unroll
            for (int kc = 0; kc < 2; kc++) {
                unsigned bh2[2], bl2[2];
                int o = kc*8 + tig;
                bh2[0] = Khi[nb + o]; bh2[1] = Khi[nb + o + 4];
                bl2[0] = Klo[nb + o]; bl2[1] = Klo[nb + o + 4];
                mma_bf16(d[nt], ah[kc], bh2);
                mma_bf16(d[nt], al[kc], bh2);
                mma_bf16(d[nt], ah[kc], bl2);
            }
        }

        // ---- exp + transposed store Ss[key][q] + rowsum
        {
            int q0 = mq*16 + grp;
            #pragma unroll
            for (int nt = 0; nt < 4; nt++) {
                int k0 = kh*32 + nt*8 + tig*2;
                float w0 = __expf(d[nt][0] * SCALEF);
                float w1 = __expf(d[nt][1] * SCALEF);
                float w2 = __expf(d[nt][2] * SCALEF);
                float w3 = __expf(d[nt][3] * SCALEF);
                rs0 += w0 + w1;
                rs1 += w2 + w3;
                Ss[k0][q0]       = w0;
                Ss[k0+1][q0]     = w1;
                Ss[k0][q0+8]     = w2;
                Ss[k0+1][q0+8]   = w3;
            }
        }
        __syncthreads();

        // ---- PV: pass2's exact fp32 f2fma loop over this 64-key chunk
        #pragma unroll 8
        for (int kk = 0; kk < 64; kk++) {
            ull a0 = *(const ull*)&Ss[kk][ty*4];
            ull a1 = *(const ull*)&Ss[kk][ty*4 + 2];
            float2 bf = *(const float2*)&Vzs[kk][tx*2];
            ull b0 = f2pack(bf.x, bf.x), b1 = f2pack(bf.y, bf.y);
            acc[0][0] = f2fma(b0, a0, acc[0][0]); acc[0][1] = f2fma(b0, a1, acc[0][1]);
            acc[1][0] = f2fma(b1, a0, acc[1][0]); acc[1][1] = f2fma(b1, a1, acc[1][1]);
        }
        __syncthreads();   // before next chunk overwrites Ss/K/Vzs
    }

    // ---- L: reduce rowsums (per kh half), then invert
    {
        rs0 += __shfl_xor_sync(0xffffffffu, rs0, 1);
        rs0 += __shfl_xor_sync(0xffffffffu, rs0, 2);
        rs1 += __shfl_xor_sync(0xffffffffu, rs1, 1);
        rs1 += __shfl_xor_sync(0xffffffffu, rs1, 2);
        if (tig == 0) {
            int q0 = mq*16 + grp;
            Lbuf[kh][q0]     = rs0;
            Lbuf[kh][q0 + 8] = rs1;
        }
    }
    __syncthreads();
    if (tid < 64) sinvL[tid] = 1.0f / (Lbuf[0][tid] + Lbuf[1][tid]);
    __syncthreads();

    // ---- power-mean epilogue (pass2's exact form)
    {
        float v[2][4];
        f2unpack(acc[0][0], v[0][0], v[0][1]); f2unpack(acc[0][1], v[0][2], v[0][3]);
        f2unpack(acc[1][0], v[1][0], v[1][1]); f2unpack(acc[1][1], v[1][2], v[1][3]);

        const int a0 = h*32 + tx*2;
        const float ip0 = g_invp[a0],            ip1 = g_invp[a0+1];
        const float us0 = g_unscale[b*256 + a0], us1 = g_unscale[b*256 + a0 + 1];
        const float vm0 = g_vmin[b*256 + a0],    vm1 = g_vmin[b*256 + a0 + 1];
        #pragma unroll
        for (int r = 0; r < 4; r++) {
            int ql = ty*4 + r;
            int q  = qt*64 + ql;
            float il = sinvL[ql];
            float e0 = __expf(__logf(v[0][r] * il) * ip0);
            float e1 = __expf(__logf(v[1][r] * il) * ip1);
            float2 o = make_float2((e0 - B_CONSTF) * us0 + vm0,
                                   (e1 - B_CONSTF) * us1 + vm1);
            *(float2*)&g_e[(size_t)(b*512 + q)*256 + a0] = o;
        }
    }
}

// =========================================================================
// Kernel 5: output projection (round-8 proven).
// =========================================================================
__global__ __launch_bounds__(256, 1) void out_gemm(const float* __restrict__ Wo,
                                                   float* __restrict__ out) {
    __shared__ float As[16][68];
    __shared__ float Bs[16][36];
    const int bn = blockIdx.x * 32;
    const int bm = blockIdx.y * 64;
    const int tid = threadIdx.x, tx = tid & 15, ty = tid >> 4;
    const int lm = tid >> 2, lc = tid & 3;
    const int ln = tid & 31, lk = tid >> 5;

    ull acc[2][2];
    acc[0][0] = acc[0][1] = acc[1][0] = acc[1][1] = 0ULL;

    float4 pa = *(const float4*)&g_e[(size_t)(bm + lm)*256 + lc*4];
    float4 pb;
    if (tid < 128) pb = *(const float4*)&Wo[(size_t)(bn + ln)*256 + lk*4];

    for (int k0 = 0; k0 < 256; k0 += 16) {
        As[lc*4+0][lm] = pa.x; As[lc*4+1][lm] = pa.y;
        As[lc*4+2][lm] = pa.z; As[lc*4+3][lm] = pa.w;
        if (tid < 128) {
            Bs[lk*4+0][ln] = pb.x; Bs[lk*4+1][ln] = pb.y;
            Bs[lk*4+2][ln] = pb.z; Bs[lk*4+3][ln] = pb.w;
        }
        __syncthreads();
        if (k0 + 16 < 256) {
            pa = *(const float4*)&g_e[(size_t)(bm + lm)*256 + k0 + 16 + lc*4];
            if (tid < 128) pb = *(const float4*)&Wo[(size_t)(bn + ln)*256 + k0 + 16 + lk*4];
        }
        #pragma unroll
        for (int kk = 0; kk < 16; kk++) {
            ull a0 = *(const ull*)&As[kk][ty*4];
            ull a1 = *(const ull*)&As[kk][ty*4+2];
            float2 bf = *(const float2*)&Bs[kk][tx*2];
            ull b0 = f2pack(bf.x, bf.x), b1 = f2pack(bf.y, bf.y);
            acc[0][0] = f2fma(b0, a0, acc[0][0]); acc[0][1] = f2fma(b0, a1, acc[0][1]);
            acc[1][0] = f2fma(b1, a0, acc[1][0]); acc[1][1] = f2fma(b1, a1, acc[1][1]);
        }
        __syncthreads();
    }
    float v[2][4];
    f2unpack(acc[0][0], v[0][0], v[0][1]); f2unpack(acc[0][1], v[0][2], v[0][3]);
    f2unpack(acc[1][0], v[1][0], v[1][1]); f2unpack(acc[1][1], v[1][2], v[1][3]);
    #pragma unroll
    for (int r = 0; r < 4; r++) {
        float2 o = make_float2(v[0][r], v[1][r]);
        *(float2*)&out[(size_t)(bm + ty*4 + r)*256 + bn + tx*2] = o;
    }
}

// ---------------- launch ----------------
extern "C" void kernel_launch(void* const* d_in, const int* in_sizes, int n_in,
                              void* d_out, int out_size) {
    const float* context = (const float*)d_in[0];
    const float* W_Q     = (const float*)d_in[1];
    const float* W_KV    = (const float*)d_in[2];
    const float* W_out   = (const float*)d_in[3];
    const float* p_param = (const float*)d_in[4];
    float* out = (float*)d_out;

    qkv_gemm    <<<dim3(12, 16),    256>>>(context, W_Q, W_KV);
    vstats_kernel<<<dim3(8, 2),     256>>>(p_param);
    vz_kernel   <<<dim3(8, 16),     256>>>();
    attn_fused  <<<dim3(8, 16),     256>>>();
    out_gemm    <<<dim3(8, 16),     256>>>(W_out, out);
}

// round 17
// speedup vs baseline: 1.3156x; 1.1100x over previous
#include <cuda_runtime.h>
#include <cuda_bf16.h>
#include <math.h>

#define B_CONSTF 0.9f
#define EPSF 1e-10f
#define SCALEF 0.0625f

typedef unsigned long long ull;

// ---------------- device scratch ----------------
__device__ float g_qh[16*512*32];    // per-head Q   [bh][s][32]
__device__ float g_kh[16*512*32];    // per-head K   [bh][s][32]
__device__ float g_v [1024*256];     // V row-major  [b*s][256]
__device__ float g_vz[16*512*32];    // v_norm^p     [bh][s][32]
__device__ float g_e [1024*256];     // power-mean result (row-major)
__device__ float g_vmin[512], g_nscale[512], g_unscale[512];
__device__ float g_p[256], g_invp[256];
// pre-split bf16 operands (packed bf16x2 words)
__device__ unsigned g_ctxh[1024*128], g_ctxl[1024*128];   // ctx  [row][128w]
__device__ unsigned g_wh  [768*128],  g_wl  [768*128];    // [W_Q;W_KV] rows

// ---------------- f32x2 helpers ----------------
__device__ __forceinline__ ull f2pack(float lo, float hi) {
    ull r; asm("mov.b64 %0, {%1, %2};" : "=l"(r) : "f"(lo), "f"(hi)); return r;
}
__device__ __forceinline__ void f2unpack(ull v, float& lo, float& hi) {
    asm("mov.b64 {%0, %1}, %2;" : "=f"(lo), "=f"(hi) : "l"(v));
}
__device__ __forceinline__ ull f2fma(ull a, ull b, ull c) {
    ull d; asm("fma.rn.f32x2 %0, %1, %2, %3;" : "=l"(d) : "l"(a), "l"(b), "l"(c)); return d;
}

// ---------------- warp mma helpers ----------------
__device__ __forceinline__ void mma_bf16(float* d, const unsigned* a, const unsigned* b) {
    asm volatile(
        "mma.sync.aligned.m16n8k16.row.col.f32.bf16.bf16.f32 "
        "{%0,%1,%2,%3}, {%4,%5,%6,%7}, {%8,%9}, {%0,%1,%2,%3};"
        : "+f"(d[0]), "+f"(d[1]), "+f"(d[2]), "+f"(d[3])
        : "r"(a[0]), "r"(a[1]), "r"(a[2]), "r"(a[3]), "r"(b[0]), "r"(b[1]));
}
__device__ __forceinline__ void ldsm_x4(unsigned& r0, unsigned& r1,
                                        unsigned& r2, unsigned& r3, unsigned addr) {
    asm volatile("ldmatrix.sync.aligned.m8n8.x4.shared.b16 {%0,%1,%2,%3}, [%4];"
        : "=r"(r0), "=r"(r1), "=r"(r2), "=r"(r3) : "r"(addr));
}
__device__ __forceinline__ unsigned smem_u32(const void* p) {
    unsigned r;
    asm("{ .reg .u64 t; cvta.to.shared.u64 t, %1; cvt.u32.u64 %0, t; }" : "=r"(r) : "l"(p));
    return r;
}
// fp32 -> (hi,lo) bf16x2 words (2-way split)
__device__ __forceinline__ void split2(float x0, float x1, unsigned& hw, unsigned& lw) {
    __nv_bfloat16 h0 = __float2bfloat16(x0);
    __nv_bfloat16 h1 = __float2bfloat16(x1);
    __nv_bfloat16 l0 = __float2bfloat16(x0 - __bfloat162float(h0));
    __nv_bfloat16 l1 = __float2bfloat16(x1 - __bfloat162float(h1));
    hw = (unsigned)__bfloat16_as_ushort(h0) | ((unsigned)__bfloat16_as_ushort(h1) << 16);
    lw = (unsigned)__bfloat16_as_ushort(l0) | ((unsigned)__bfloat16_as_ushort(l1) << 16);
}

// =========================================================================
// Kernel 0: pre-split ctx and [W_Q;W_KV] into bf16 hi/lo word arrays.
// grid 896 x 256 thr; one bf16x2 word per thread.
// =========================================================================
__global__ __launch_bounds__(256) void prep_split(
    const float* __restrict__ ctx, const float* __restrict__ W_Q,
    const float* __restrict__ W_KV)
{
    int idx = blockIdx.x * 256 + threadIdx.x;
    if (idx < 1024*128) {
        float2 x = *(const float2*)&ctx[(size_t)idx * 2];
        split2(x.x, x.y, g_ctxh[idx], g_ctxl[idx]);
    } else if (idx < 1024*128 + 768*128) {
        int i2 = idx - 1024*128;
        int row = i2 >> 7, wc = i2 & 127;
        const float* src = (row < 256) ? &W_Q [(size_t)row*256 + wc*2]
                                       : &W_KV[(size_t)(row-256)*256 + wc*2];
        float2 x = *(const float2*)src;
        split2(x.x, x.y, g_wh[i2], g_wl[i2]);
    }
}

// =========================================================================
// Kernel 1: QKV projection on tensor cores (split-bf16, 3 terms).
// C[1024][768] = ctx @ [W_Q;W_KV]^T.  grid (12 bn, 16 bm) = 192 blocks,
// 256 thr (8 warps). Tile 64m x 64n, K=256 in 8 chunks of 32.
// Warp w: wm=(w&1)*32, wn=(w>>1)*16 -> 32m x 16n (2mt x 2nt m16n8 tiles).
// ldmatrix feeds (round-13 validated mappings, PW=20).
// Epilogue scatters to g_qh / g_kh / g_v (byte-exact vs old kernel).
// =========================================================================
#define PW 20

__global__ __launch_bounds__(256, 1) void qkv_mma() {
    __shared__ unsigned Ah[64*PW], Al[64*PW];
    __shared__ unsigned Bh[64*PW], Bl[64*PW];
    const int tid = threadIdx.x, lane = tid & 31, w = tid >> 5;
    const int tig = lane & 3, grp = lane >> 2;
    const int bn = blockIdx.x * 64, bm = blockIdx.y * 64;
    const int wm = (w & 1) * 32, wn = (w >> 1) * 16;

    const unsigned ahB = smem_u32(Ah), alB = smem_u32(Al);
    const unsigned bhB = smem_u32(Bh), blB = smem_u32(Bl);

    float d[2][2][4];
    #pragma unroll
    for (int mt = 0; mt < 2; mt++)
        #pragma unroll
        for (int nt = 0; nt < 2; nt++)
            #pragma unroll
            for (int i = 0; i < 4; i++) d[mt][nt][i] = 0.f;

    const int frow = tid >> 2, fpart = tid & 3;

    for (int kc8 = 0; kc8 < 8; kc8++) {
        // ---- fill A (ctx rows) and B (W rows), 16 words per row
        {
            size_t abase = (size_t)(bm + frow)*128 + kc8*16 + fpart*4;
            *(uint4*)&Ah[frow*PW + fpart*4] = *(const uint4*)&g_ctxh[abase];
            *(uint4*)&Al[frow*PW + fpart*4] = *(const uint4*)&g_ctxl[abase];
            size_t bbase = (size_t)(bn + frow)*128 + kc8*16 + fpart*4;
            *(uint4*)&Bh[frow*PW + fpart*4] = *(const uint4*)&g_wh[bbase];
            *(uint4*)&Bl[frow*PW + fpart*4] = *(const uint4*)&g_wl[bbase];
        }
        __syncthreads();

        // ---- A fragments: [mt][kc][4], hi and lo (ldmatrix.x4)
        unsigned ah[2][2][4], al[2][2][4];
        #pragma unroll
        for (int mt = 0; mt < 2; mt++) {
            unsigned rowoff = (unsigned)((wm + mt*16 + (lane & 15)) * (PW*4))
                            + ((lane >> 4) & 1) * 16;
            #pragma unroll
            for (int kc = 0; kc < 2; kc++) {
                ldsm_x4(ah[mt][kc][0], ah[mt][kc][1], ah[mt][kc][2], ah[mt][kc][3],
                        ahB + rowoff + kc*32);
                ldsm_x4(al[mt][kc][0], al[mt][kc][1], al[mt][kc][2], al[mt][kc][3],
                        alB + rowoff + kc*32);
            }
        }
        // ---- B fragments: x4 covers nt pair {0,1}: [nt][kc][2]
        unsigned bfh[2][2][2], bfl[2][2][2];
        {
            unsigned rowoff = (unsigned)((wn + ((lane >> 4) & 1)*8 + (lane & 7)) * (PW*4))
                            + ((lane >> 3) & 1) * 16;
            #pragma unroll
            for (int kc = 0; kc < 2; kc++) {
                unsigned m0, m1, m2, m3;
                ldsm_x4(m0, m1, m2, m3, bhB + rowoff + kc*32);
                bfh[0][kc][0] = m0; bfh[0][kc][1] = m1;
                bfh[1][kc][0] = m2; bfh[1][kc][1] = m3;
                ldsm_x4(m0, m1, m2, m3, blB + rowoff + kc*32);
                bfl[0][kc][0] = m0; bfl[0][kc][1] = m1;
                bfl[1][kc][0] = m2; bfl[1][kc][1] = m3;
            }
        }
        // ---- MMAs: 2mt x 2nt x 2kc x 3 terms
        #pragma unroll
        for (int mt = 0; mt < 2; mt++)
            #pragma unroll
            for (int nt = 0; nt < 2; nt++)
                #pragma unroll
                for (int kc = 0; kc < 2; kc++) {
                    mma_bf16(d[mt][nt], ah[mt][kc], bfh[nt][kc]);   // hi*hi
                    mma_bf16(d[mt][nt], al[mt][kc], bfh[nt][kc]);   // lo*hi
                    mma_bf16(d[mt][nt], ah[mt][kc], bfl[nt][kc]);   // hi*lo
                }
        __syncthreads();
    }

    // ---- epilogue: scatter to g_qh / g_kh / g_v (same mapping as before)
    #pragma unroll
    for (int mt = 0; mt < 2; mt++)
        #pragma unroll
        for (int nt = 0; nt < 2; nt++) {
            int c = bn + wn + nt*8 + tig*2;
            #pragma unroll
            for (int half = 0; half < 2; half++) {
                int row = bm + wm + mt*16 + grp + half*8;
                float2 o = make_float2(d[mt][nt][half*2], d[mt][nt][half*2 + 1]);
                int b = row >> 9, s = row & 511;
                if (c < 256) {
                    int h = c >> 5, a = c & 31;
                    *(float2*)&g_qh[((size_t)((b*8+h)*512 + s))*32 + a] = o;
                } else if (c < 512) {
                    int kc2 = c - 256, h = kc2 >> 5, a = kc2 & 31;
                    *(float2*)&g_kh[((size_t)((b*8+h)*512 + s))*32 + a] = o;
                } else {
                    *(float2*)&g_v[(size_t)row * 256 + (c - 512)] = o;
                }
            }
        }
}

// =========================================================================
// Kernel 2: v min/max per (b,d) + p/invp.
// =========================================================================
__global__ __launch_bounds__(256) void vstats_kernel(const float* __restrict__ p_param) {
    __shared__ float smn[8][32], smx[8][32];
    const int b = blockIdx.y, dc = blockIdx.x;
    const int dd = threadIdx.x & 31, sl = threadIdx.x >> 5;
    const int d = dc*32 + dd;
    float mn = 1e30f, mx = -1e30f;
    const float* base = g_v + (size_t)(b*512 + sl*64) * 256 + d;
    #pragma unroll 4
    for (int i = 0; i < 64; i++) {
        float v = base[(size_t)i * 256];
        mn = fminf(mn, v); mx = fmaxf(mx, v);
    }
    smn[sl][dd] = mn; smx[sl][dd] = mx;
    __syncthreads();
    if (sl == 0) {
        #pragma unroll
        for (int t = 1; t < 8; t++) {
            mn = fminf(mn, smn[t][dd]); mx = fmaxf(mx, smx[t][dd]);
        }
        float range = mx - mn + EPSF;
        g_vmin   [b*256 + d] = mn;
        g_nscale [b*256 + d] = (1.0f - B_CONSTF) / range;
        g_unscale[b*256 + d] = range / (1.0f - B_CONSTF);
        if (b == 0) {
            float pp = p_param[d];
            float p  = 50000.0f * tanhf(0.005f * pp) + 1.0f;
            if (p == 0.0f) p = 1e-4f;
            g_p[d] = p; g_invp[d] = 1.0f / p;
        }
    }
}

// =========================================================================
// Kernel 3: vz = v_norm^p per-head.
// =========================================================================
__global__ __launch_bounds__(256) void vz_kernel() {
    __shared__ float s_p[32], s_ns[32], s_vm[32];
    const int bh = blockIdx.y, sc = blockIdx.x;
    const int b = bh >> 3, h = bh & 7;
    const int tid = threadIdx.x;
    if (tid < 32) {
        int d = h*32 + tid;
        s_p[tid]  = g_p[d];
        s_ns[tid] = g_nscale[b*256 + d];
        s_vm[tid] = g_vmin[b*256 + d];
    }
    __syncthreads();
    const int a = tid & 31, sq = tid >> 5;
    #pragma unroll
    for (int it = 0; it < 8; it++) {
        int s = sc*64 + it*8 + sq;
        float v  = g_v[(size_t)(b*512 + s) * 256 + h*32 + a];
        float vn = (v - s_vm[a]) * s_ns[a] + B_CONSTF;
        g_vz[((size_t)(bh*512 + s))*32 + a] = __expf(s_p[a] * __logf(vn));
    }
}

// =========================================================================
// Kernel 4: FUSED attention (round-16 passing version, unchanged).
// =========================================================================
__global__ __launch_bounds__(256, 1) void attn_fused() {
    __shared__ unsigned Qhi[64*PW], Qlo[64*PW];
    __shared__ unsigned Khi[64*PW], Klo[64*PW];
    __shared__ float Ss[64][66];
    __shared__ float Vzs[64][36];
    __shared__ float Lbuf[2][64];
    __shared__ float sinvL[64];

    const int tid = threadIdx.x, lane = tid & 31, w = tid >> 5;
    const int tig = lane & 3, grp = lane >> 2;
    const int qt = blockIdx.x, bh = blockIdx.y;
    const int b = bh >> 3, h = bh & 7;
    const int mq = w & 3, kh = w >> 2;
    const int tx = tid & 15, ty = tid >> 4;

    {
        int row = tid >> 2, part = tid & 3;
        const float* src = g_qh + ((size_t)bh*512 + qt*64 + row)*32 + part*8;
        float4 x0 = *(const float4*)&src[0];
        float4 x1 = *(const float4*)&src[4];
        unsigned hw, lw;
        split2(x0.x, x0.y, hw, lw); Qhi[row*PW + part*4 + 0] = hw; Qlo[row*PW + part*4 + 0] = lw;
        split2(x0.z, x0.w, hw, lw); Qhi[row*PW + part*4 + 1] = hw; Qlo[row*PW + part*4 + 1] = lw;
        split2(x1.x, x1.y, hw, lw); Qhi[row*PW + part*4 + 2] = hw; Qlo[row*PW + part*4 + 2] = lw;
        split2(x1.z, x1.w, hw, lw); Qhi[row*PW + part*4 + 3] = hw; Qlo[row*PW + part*4 + 3] = lw;
    }
    __syncthreads();

    unsigned ah[2][4], al[2][4];
    {
        int r0 = (mq*16 + grp) * PW, r1 = r0 + 8*PW;
        #pragma unroll
        for (int kc = 0; kc < 2; kc++) {
            int o = kc*8 + tig;
            ah[kc][0] = Qhi[r0 + o];     ah[kc][1] = Qhi[r1 + o];
            ah[kc][2] = Qhi[r0 + o + 4]; ah[kc][3] = Qhi[r1 + o + 4];
            al[kc][0] = Qlo[r0 + o];     al[kc][1] = Qlo[r1 + o];
            al[kc][2] = Qlo[r0 + o + 4]; al[kc][3] = Qlo[r1 + o + 4];
        }
    }

    ull acc[2][2];
    acc[0][0] = acc[0][1] = acc[1][0] = acc[1][1] = 0ULL;
    float rs0 = 0.f, rs1 = 0.f;

    for (int it = 0; it < 8; it++) {
        {
            int row = tid >> 2, part = tid & 3;
            const float* src = g_kh + ((size_t)bh*512 + it*64 + row)*32 + part*8;
            float4 x0 = *(const float4*)&src[0];
            float4 x1 = *(const float4*)&src[4];
            unsigned hw, lw;
            split2(x0.x, x0.y, hw, lw); Khi[row*PW + part*4 + 0] = hw; Klo[row*PW + part*4 + 0] = lw;
            split2(x0.z, x0.w, hw, lw); Khi[row*PW + part*4 + 1] = hw; Klo[row*PW + part*4 + 1] = lw;
            split2(x1.x, x1.y, hw, lw); Khi[row*PW + part*4 + 2] = hw; Klo[row*PW + part*4 + 2] = lw;
            split2(x1.z, x1.w, hw, lw); Khi[row*PW + part*4 + 3] = hw; Klo[row*PW + part*4 + 3] = lw;

            const float* vs = g_vz + ((size_t)bh*512 + it*64 + row)*32 + part*8;
            *(float4*)&Vzs[row][part*8]     = *(const float4*)&vs[0];
            *(float4*)&Vzs[row][part*8 + 4] = *(const float4*)&vs[4];
        }
        __syncthreads();

        float d[4][4];
        #pragma unroll
        for (int n = 0; n < 4; n++)
            #pragma unroll
            for (int i = 0; i < 4; i++) d[n][i] = 0.f;

        #pragma unroll
        for (int nt = 0; nt < 4; nt++) {
            int nb = (kh*32 + nt*8 + grp) * PW;
            #pragma unroll
            for (int kc = 0; kc < 2; kc++) {
                unsigned bh2[2], bl2[2];
                int o = kc*8 + tig;
                bh2[0] = Khi[nb + o]; bh2[1] = Khi[nb + o + 4];
                bl2[0] = Klo[nb + o]; bl2[1] = Klo[nb + o + 4];
                mma_bf16(d[nt], ah[kc], bh2);
                mma_bf16(d[nt], al[kc], bh2);
                mma_bf16(d[nt], ah[kc], bl2);
            }
        }

        {
            int q0 = mq*16 + grp;
            #pragma unroll
            for (int nt = 0; nt < 4; nt++) {
                int k0 = kh*32 + nt*8 + tig*2;
                float w0 = __expf(d[nt][0] * SCALEF);
                float w1 = __expf(d[nt][1] * SCALEF);
                float w2 = __expf(d[nt][2] * SCALEF);
                float w3 = __expf(d[nt][3] * SCALEF);
                rs0 += w0 + w1;
                rs1 += w2 + w3;
                Ss[k0][q0]       = w0;
                Ss[k0+1][q0]     = w1;
                Ss[k0][q0+8]     = w2;
                Ss[k0+1][q0+8]   = w3;
            }
        }
        __syncthreads();

        #pragma unroll 8
        for (int kk = 0; kk < 64; kk++) {
            ull a0 = *(const ull*)&Ss[kk][ty*4];
            ull a1 = *(const ull*)&Ss[kk][ty*4 + 2];
            float2 bf = *(const float2*)&Vzs[kk][tx*2];
            ull b0 = f2pack(bf.x, bf.x), b1 = f2pack(bf.y, bf.y);
            acc[0][0] = f2fma(b0, a0, acc[0][0]); acc[0][1] = f2fma(b0, a1, acc[0][1]);
            acc[1][0] = f2fma(b1, a0, acc[1][0]); acc[1][1] = f2fma(b1, a1, acc[1][1]);
        }
        __syncthreads();
    }

    {
        rs0 += __shfl_xor_sync(0xffffffffu, rs0, 1);
        rs0 += __shfl_xor_sync(0xffffffffu, rs0, 2);
        rs1 += __shfl_xor_sync(0xffffffffu, rs1, 1);
        rs1 += __shfl_xor_sync(0xffffffffu, rs1, 2);
        if (tig == 0) {
            int q0 = mq*16 + grp;
            Lbuf[kh][q0]     = rs0;
            Lbuf[kh][q0 + 8] = rs1;
        }
    }
    __syncthreads();
    if (tid < 64) sinvL[tid] = 1.0f / (Lbuf[0][tid] + Lbuf[1][tid]);
    __syncthreads();

    {
        float v[2][4];
        f2unpack(acc[0][0], v[0][0], v[0][1]); f2unpack(acc[0][1], v[0][2], v[0][3]);
        f2unpack(acc[1][0], v[1][0], v[1][1]); f2unpack(acc[1][1], v[1][2], v[1][3]);

        const int a0 = h*32 + tx*2;
        const float ip0 = g_invp[a0],            ip1 = g_invp[a0+1];
        const float us0 = g_unscale[b*256 + a0], us1 = g_unscale[b*256 + a0 + 1];
        const float vm0 = g_vmin[b*256 + a0],    vm1 = g_vmin[b*256 + a0 + 1];
        #pragma unroll
        for (int r = 0; r < 4; r++) {
            int ql = ty*4 + r;
            int q  = qt*64 + ql;
            float il = sinvL[ql];
            float e0 = __expf(__logf(v[0][r] * il) * ip0);
            float e1 = __expf(__logf(v[1][r] * il) * ip1);
            float2 o = make_float2((e0 - B_CONSTF) * us0 + vm0,
                                   (e1 - B_CONSTF) * us1 + vm1);
            *(float2*)&g_e[(size_t)(b*512 + q)*256 + a0] = o;
        }
    }
}

// =========================================================================
// Kernel 5: output projection (round-8 proven).
// =========================================================================
__global__ __launch_bounds__(256, 1) void out_gemm(const float* __restrict__ Wo,
                                                   float* __restrict__ out) {
    __shared__ float As[16][68];
    __shared__ float Bs[16][36];
    const int bn = blockIdx.x * 32;
    const int bm = blockIdx.y * 64;
    const int tid = threadIdx.x, tx = tid & 15, ty = tid >> 4;
    const int lm = tid >> 2, lc = tid & 3;
    const int ln = tid & 31, lk = tid >> 5;

    ull acc[2][2];
    acc[0][0] = acc[0][1] = acc[1][0] = acc[1][1] = 0ULL;

    float4 pa = *(const float4*)&g_e[(size_t)(bm + lm)*256 + lc*4];
    float4 pb;
    if (tid < 128) pb = *(const float4*)&Wo[(size_t)(bn + ln)*256 + lk*4];

    for (int k0 = 0; k0 < 256; k0 += 16) {
        As[lc*4+0][lm] = pa.x; As[lc*4+1][lm] = pa.y;
        As[lc*4+2][lm] = pa.z; As[lc*4+3][lm] = pa.w;
        if (tid < 128) {
            Bs[lk*4+0][ln] = pb.x; Bs[lk*4+1][ln] = pb.y;
            Bs[lk*4+2][ln] = pb.z; Bs[lk*4+3][ln] = pb.w;
        }
        __syncthreads();
        if (k0 + 16 < 256) {
            pa = *(const float4*)&g_e[(size_t)(bm + lm)*256 + k0 + 16 + lc*4];
            if (tid < 128) pb = *(const float4*)&Wo[(size_t)(bn + ln)*256 + k0 + 16 + lk*4];
        }
        #pragma unroll
        for (int kk = 0; kk < 16; kk++) {
            ull a0 = *(const ull*)&As[kk][ty*4];
            ull a1 = *(const ull*)&As[kk][ty*4+2];
            float2 bf = *(const float2*)&Bs[kk][tx*2];
            ull b0 = f2pack(bf.x, bf.x), b1 = f2pack(bf.y, bf.y);
            acc[0][0] = f2fma(b0, a0, acc[0][0]); acc[0][1] = f2fma(b0, a1, acc[0][1]);
            acc[1][0] = f2fma(b1, a0, acc[1][0]); acc[1][1] = f2fma(b1, a1, acc[1][1]);
        }
        __syncthreads();
    }
    float v[2][4];
    f2unpack(acc[0][0], v[0][0], v[0][1]); f2unpack(acc[0][1], v[0][2], v[0][3]);
    f2unpack(acc[1][0], v[1][0], v[1][1]); f2unpack(acc[1][1], v[1][2], v[1][3]);
    #pragma unroll
    for (int r = 0; r < 4; r++) {
        float2 o = make_float2(v[0][r], v[1][r]);
        *(float2*)&out[(size_t)(bm + ty*4 + r)*256 + bn + tx*2] = o;
    }
}

// ---------------- launch ----------------
extern "C" void kernel_launch(void* const* d_in, const int* in_sizes, int n_in,
                              void* d_out, int out_size) {
    const float* context = (const float*)d_in[0];
    const float* W_Q     = (const float*)d_in[1];
    const float* W_KV    = (const float*)d_in[2];
    const float* W_out   = (const float*)d_in[3];
    const float* p_param = (const float*)d_in[4];
    float* out = (float*)d_out;

    prep_split  <<<896,              256>>>(context, W_Q, W_KV);
    qkv_mma     <<<dim3(12, 16),     256>>>();
    vstats_kernel<<<dim3(8, 2),      256>>>(p_param);
    vz_kernel   <<<dim3(8, 16),      256>>>();
    attn_fused  <<<dim3(8, 16),      256>>>();
    out_gemm    <<<dim3(8, 16),      256>>>(W_out, out);
}